// round 4
// baseline (speedup 1.0000x reference)
#include <cuda_runtime.h>

#define NW 10
#define DIM 1024
#define WARPS_PER_BLK 4

typedef unsigned long long u64;

// ---- packed f32x2 primitives ----
__device__ __forceinline__ u64 pk(float x, float y) {
    u64 r; asm("mov.b64 %0,{%1,%2};" : "=l"(r) : "f"(x), "f"(y)); return r;
}
__device__ __forceinline__ u64 pkb(float x) { return pk(x, x); }
__device__ __forceinline__ void upk(u64 a, float& x, float& y) {
    asm("mov.b64 {%0,%1},%2;" : "=f"(x), "=f"(y) : "l"(a));
}
__device__ __forceinline__ u64 f2fma(u64 a, u64 b, u64 c) {
    u64 d; asm("fma.rn.f32x2 %0,%1,%2,%3;" : "=l"(d) : "l"(a), "l"(b), "l"(c)); return d;
}
__device__ __forceinline__ u64 f2mul(u64 a, u64 b) {
    u64 d; asm("mul.rn.f32x2 %0,%1,%2;" : "=l"(d) : "l"(a), "l"(b)); return d;
}
__device__ __forceinline__ u64 f2add(u64 a, u64 b) {
    u64 d; asm("add.rn.f32x2 %0,%1,%2;" : "=l"(d) : "l"(a), "l"(b)); return d;
}
// swap halves (re,im)->(im,re)
__device__ __forceinline__ u64 swp(u64 a) {
    float x, y; upk(a, x, y); return pk(y, x);
}
// volatile shared load: prevents ptxas from hoisting coefficients across gates
__device__ __forceinline__ u64 ldsv(const u64* p) {
    return *(const volatile u64*)p;
}

// XOR swizzle for conflict-free 32x32 8-byte transpose through shared memory.
__device__ __forceinline__ int swz(int idx) {
    return (idx & 0x3E0) | (((idx >> 5) ^ idx) & 31);
}

// CNOT-ring gather: psi_after[i] = psi_before[g(i)]
__device__ __forceinline__ int cnot_gather(int i) {
    return i ^ (i >> 1) ^ ((i & 1) << 8) ^ ((i & 1) << 9);
}

// Fused layer-1 gate on register bit K; coefficients loaded (volatile) from shared.
// cf layout: [0]=arr (ar,ar)  [1]=naiai (-ai,ai)  [2]=ainai (ai,-ai)
//            [3]=brr (br,br)  [4]=nbrbr (-br,-br) [5]=nbibi (-bi,bi)
template<int K>
__device__ __forceinline__ void l1c(u64* a, const u64* cf) {
    const u64 arr = ldsv(cf + 0), naiai = ldsv(cf + 1), ainai = ldsv(cf + 2);
    const u64 brr = ldsv(cf + 3), nbrbr = ldsv(cf + 4), nbibi = ldsv(cf + 5);
#pragma unroll
    for (int p = 0; p < 16; ++p) {
        const int m0 = ((p >> K) << (K + 1)) | (p & ((1 << K) - 1));
        const int m1 = m0 | (1 << K);
        u64 a0 = a[m0], a1 = a[m1];
        u64 s0 = swp(a0), s1 = swp(a1);
        u64 n0 = f2fma(arr,   a0, f2fma(naiai, s0, f2fma(brr, a1, f2mul(nbibi, s1))));
        u64 n1 = f2fma(nbrbr, a0, f2fma(nbibi, s0, f2fma(arr, a1, f2mul(ainai, s1))));
        a[m0] = n0; a[m1] = n1;
    }
}

// RY gate on register bit K. cf: [0]=cc [1]=ss [2]=nss
template<int K>
__device__ __forceinline__ void ryc(u64* a, const u64* cf) {
    const u64 cc = ldsv(cf + 0), ss = ldsv(cf + 1), nss = ldsv(cf + 2);
#pragma unroll
    for (int p = 0; p < 16; ++p) {
        const int m0 = ((p >> K) << (K + 1)) | (p & ((1 << K) - 1));
        const int m1 = m0 | (1 << K);
        u64 n0 = f2fma(cc, a[m0], f2mul(nss, a[m1]));
        u64 n1 = f2fma(ss, a[m0], f2mul(cc,  a[m1]));
        a[m0] = n0; a[m1] = n1;
    }
}

__global__ __launch_bounds__(128, 4)
void qsa4_kernel(const float* __restrict__ x,
                 const float* __restrict__ rx0,
                 const float* __restrict__ ry0,
                 const float* __restrict__ ry1,
                 float* __restrict__ out)
{
    __shared__ u64 buf[WARPS_PER_BLK][DIM];   // 8 KB per warp
    __shared__ u64 cl1[NW][6];                // packed layer-1 coeffs
    __shared__ u64 cry[NW][3];                // packed layer-2 RY coeffs
    __shared__ u64 cw0[4];                    // wire-0 real-input special gate

    const int tid = threadIdx.x;
    if (tid < NW) {
        float s, c, s0, c0, s1, c1;
        sincosf(0.5f * rx0[tid], &s,  &c);
        sincosf(0.5f * ry0[tid], &s0, &c0);
        sincosf(0.5f * ry1[tid], &s1, &c1);
        const float ar =  c0 * c;
        const float ai =  s0 * s;
        const float br = -s0 * c;
        const float bi = -c0 * s;
        cl1[tid][0] = pkb(ar);
        cl1[tid][1] = pk(-ai,  ai);
        cl1[tid][2] = pk( ai, -ai);
        cl1[tid][3] = pkb(br);
        cl1[tid][4] = pkb(-br);
        cl1[tid][5] = pk(-bi, bi);
        cry[tid][0] = pkb(c1);
        cry[tid][1] = pkb(s1);
        cry[tid][2] = pkb(-s1);
        if (tid == 0) {
            cw0[0] = pk( ar,  ai);
            cw0[1] = pk( br,  bi);
            cw0[2] = pk(-br,  bi);
            cw0[3] = pk( ar, -ai);
        }
    }
    __syncthreads();

    const int w = tid >> 5;
    const int t = tid & 31;
    const int n = blockIdx.x * WARPS_PER_BLK + w;   // state 0..4095
    u64* sb = buf[w];

    // ---- Load + L2-normalize. Layout LA: i = (r<<5)|t. ----
    float v[32];
    const float* xr = x + (size_t)n * DIM;
    float sumsq = 0.f;
#pragma unroll
    for (int r = 0; r < 32; ++r) {
        v[r] = xr[(r << 5) + t];
        sumsq += v[r] * v[r];
    }
#pragma unroll
    for (int off = 16; off; off >>= 1)
        sumsq += __shfl_xor_sync(0xffffffffu, sumsq, off);
    const float inv = 1.f / fmaxf(sqrtf(sumsq), 1e-12f);
#pragma unroll
    for (int r = 0; r < 32; ++r) v[r] *= inv;

    // ---- Phase A: fused layer-1 on wires 0..4 (wire q -> reg bit K=4-q) ----
    u64 a[32];
    {   // wire 0 (K=4), specialized for purely-real input
        const u64 pa = ldsv(cw0 + 0), pb = ldsv(cw0 + 1);
        const u64 pc = ldsv(cw0 + 2), pd = ldsv(cw0 + 3);
#pragma unroll
        for (int p = 0; p < 16; ++p) {
            u64 a0 = pkb(v[p]), a1 = pkb(v[p + 16]);
            a[p]      = f2fma(a0, pa, f2mul(a1, pb));
            a[p + 16] = f2fma(a0, pc, f2mul(a1, pd));
        }
    }
    l1c<3>(a, cl1[1]);
    l1c<2>(a, cl1[2]);
    l1c<1>(a, cl1[3]);
    l1c<0>(a, cl1[4]);

    // ---- Remap LA -> LB (transpose) ----
    __syncwarp();
#pragma unroll
    for (int r = 0; r < 32; ++r) sb[swz((r << 5) | t)] = a[r];
    __syncwarp();
#pragma unroll
    for (int r = 0; r < 32; ++r) a[r] = sb[swz((t << 5) | r)];

    // ---- Phase B: fused layer-1 on wires 5..9 (wire q -> reg bit K=9-q) ----
    l1c<4>(a, cl1[5]);
    l1c<3>(a, cl1[6]);
    l1c<2>(a, cl1[7]);
    l1c<1>(a, cl1[8]);
    l1c<0>(a, cl1[9]);

    // ---- Remap LB -> LA with the CNOT-ring gather folded in ----
    __syncwarp();
#pragma unroll
    for (int r = 0; r < 32; ++r) sb[swz((t << 5) | r)] = a[r];
    __syncwarp();
#pragma unroll
    for (int r = 0; r < 32; ++r) a[r] = sb[swz(cnot_gather((r << 5) | t))];

    // ---- Phase C: layer-2 RY on wires 0..4 ----
    ryc<4>(a, cry[0]);
    ryc<3>(a, cry[1]);
    ryc<2>(a, cry[2]);
    ryc<1>(a, cry[3]);
    ryc<0>(a, cry[4]);

    // ---- Remap LA -> LB (transpose) ----
    __syncwarp();
#pragma unroll
    for (int r = 0; r < 32; ++r) sb[swz((r << 5) | t)] = a[r];
    __syncwarp();
#pragma unroll
    for (int r = 0; r < 32; ++r) a[r] = sb[swz((t << 5) | r)];

    // ---- Phase D: layer-2 RY on wires 5..9 ----
    ryc<4>(a, cry[5]);
    ryc<3>(a, cry[6]);
    ryc<2>(a, cry[7]);
    ryc<1>(a, cry[8]);
    ryc<0>(a, cry[9]);

    // ---- Z expectations. Layout LB: i = (t<<5)|r. Packed (re^2, im^2) accum. ----
    u64 tot = 0, S0 = 0, S1 = 0, S2 = 0, S3 = 0, S4 = 0;
    const u64 NEG1 = pkb(-1.0f);
#pragma unroll
    for (int r = 0; r < 32; ++r) {
        u64 p = f2mul(a[r], a[r]);                  // (re^2, im^2)
        tot = f2add(tot, p);
        S0 = (r & 1)  ? f2fma(p, NEG1, S0) : f2add(S0, p);
        S1 = (r & 2)  ? f2fma(p, NEG1, S1) : f2add(S1, p);
        S2 = (r & 4)  ? f2fma(p, NEG1, S2) : f2add(S2, p);
        S3 = (r & 8)  ? f2fma(p, NEG1, S3) : f2add(S3, p);
        S4 = (r & 16) ? f2fma(p, NEG1, S4) : f2add(S4, p);
    }
    // horizontal: prob = re^2 + im^2
    float vals[10];
    {
        float xx, yy;
        upk(tot, xx, yy); float ft = xx + yy;
        vals[0] = (t & 16) ? -ft : ft;   // wire 0: t bit 4
        vals[1] = (t & 8)  ? -ft : ft;
        vals[2] = (t & 4)  ? -ft : ft;
        vals[3] = (t & 2)  ? -ft : ft;
        vals[4] = (t & 1)  ? -ft : ft;
        upk(S4, xx, yy); vals[5] = xx + yy;   // wire 5: r bit 4
        upk(S3, xx, yy); vals[6] = xx + yy;
        upk(S2, xx, yy); vals[7] = xx + yy;
        upk(S1, xx, yy); vals[8] = xx + yy;
        upk(S0, xx, yy); vals[9] = xx + yy;
    }
#pragma unroll
    for (int off = 16; off; off >>= 1) {
#pragma unroll
        for (int j = 0; j < 10; ++j)
            vals[j] += __shfl_xor_sync(0xffffffffu, vals[j], off);
    }
    if (t == 0) {
#pragma unroll
        for (int j = 0; j < 10; ++j) out[(size_t)n * NW + j] = vals[j];
    }
}

extern "C" void kernel_launch(void* const* d_in, const int* in_sizes, int n_in,
                              void* d_out, int out_size) {
    const float* x   = (const float*)d_in[0];
    const float* rx0 = (const float*)d_in[1];
    const float* ry0 = (const float*)d_in[2];
    const float* ry1 = (const float*)d_in[3];
    float* out = (float*)d_out;
    const int n_states = in_sizes[0] / DIM;            // 4096
    qsa4_kernel<<<n_states / WARPS_PER_BLK, 32 * WARPS_PER_BLK>>>(x, rx0, ry0, ry1, out);
}

// round 5
// speedup vs baseline: 1.6978x; 1.6978x over previous
#include <cuda_runtime.h>

#define NW 10
#define DIM 1024
#define WARPS_PER_BLK 4

typedef unsigned long long u64;

// ---- packed f32x2 primitives ----
__device__ __forceinline__ u64 pk(float x, float y) {
    u64 r; asm("mov.b64 %0,{%1,%2};" : "=l"(r) : "f"(x), "f"(y)); return r;
}
__device__ __forceinline__ u64 pkb(float x) { return pk(x, x); }
__device__ __forceinline__ void upk(u64 a, float& x, float& y) {
    asm("mov.b64 {%0,%1},%2;" : "=f"(x), "=f"(y) : "l"(a));
}
__device__ __forceinline__ u64 f2fma(u64 a, u64 b, u64 c) {
    u64 d; asm("fma.rn.f32x2 %0,%1,%2,%3;" : "=l"(d) : "l"(a), "l"(b), "l"(c)); return d;
}
__device__ __forceinline__ u64 f2mul(u64 a, u64 b) {
    u64 d; asm("mul.rn.f32x2 %0,%1,%2;" : "=l"(d) : "l"(a), "l"(b)); return d;
}
__device__ __forceinline__ u64 f2add(u64 a, u64 b) {
    u64 d; asm("add.rn.f32x2 %0,%1,%2;" : "=l"(d) : "l"(a), "l"(b)); return d;
}
// swap halves (re,im)->(im,re)
__device__ __forceinline__ u64 swp(u64 a) {
    float x, y; upk(a, x, y); return pk(y, x);
}
// volatile shared load: prevents ptxas from hoisting coefficients across gates
__device__ __forceinline__ u64 ldsv(const u64* p) {
    return *(const volatile u64*)p;
}

// XOR swizzle for conflict-free 32x32 8-byte transpose through shared memory.
__device__ __forceinline__ int swz(int idx) {
    return (idx & 0x3E0) | (((idx >> 5) ^ idx) & 31);
}

// CNOT-ring gather: psi_after[i] = psi_before[g(i)]
__device__ __forceinline__ int cnot_gather(int i) {
    return i ^ (i >> 1) ^ ((i & 1) << 8) ^ ((i & 1) << 9);
}

// Fused layer-1 gate on register bit K; coefficients loaded (volatile) from shared.
template<int K>
__device__ __forceinline__ void l1c(u64* a, const u64* cf) {
    const u64 arr = ldsv(cf + 0), naiai = ldsv(cf + 1), ainai = ldsv(cf + 2);
    const u64 brr = ldsv(cf + 3), nbrbr = ldsv(cf + 4), nbibi = ldsv(cf + 5);
#pragma unroll
    for (int p = 0; p < 16; ++p) {
        const int m0 = ((p >> K) << (K + 1)) | (p & ((1 << K) - 1));
        const int m1 = m0 | (1 << K);
        u64 a0 = a[m0], a1 = a[m1];
        u64 s0 = swp(a0), s1 = swp(a1);
        u64 n0 = f2fma(arr,   a0, f2fma(naiai, s0, f2fma(brr, a1, f2mul(nbibi, s1))));
        u64 n1 = f2fma(nbrbr, a0, f2fma(nbibi, s0, f2fma(arr, a1, f2mul(ainai, s1))));
        a[m0] = n0; a[m1] = n1;
    }
}

// RY gate on register bit K. cf: [0]=cc [1]=ss [2]=nss
template<int K>
__device__ __forceinline__ void ryc(u64* a, const u64* cf) {
    const u64 cc = ldsv(cf + 0), ss = ldsv(cf + 1), nss = ldsv(cf + 2);
#pragma unroll
    for (int p = 0; p < 16; ++p) {
        const int m0 = ((p >> K) << (K + 1)) | (p & ((1 << K) - 1));
        const int m1 = m0 | (1 << K);
        u64 n0 = f2fma(cc, a[m0], f2mul(nss, a[m1]));
        u64 n1 = f2fma(ss, a[m0], f2mul(cc,  a[m1]));
        a[m0] = n0; a[m1] = n1;
    }
}

__global__ __launch_bounds__(128, 4)
void qsa5_kernel(const float* __restrict__ x,
                 const float* __restrict__ rx0,
                 const float* __restrict__ ry0,
                 const float* __restrict__ ry1,
                 float* __restrict__ out)
{
    __shared__ u64 buf[WARPS_PER_BLK][DIM];   // 8 KB per warp
    __shared__ u64 cl1[NW][6];                // packed layer-1 coeffs
    __shared__ u64 cry[NW][3];                // packed layer-2 RY coeffs
    __shared__ u64 cw0[4];                    // wire-0 real-input special gate

    const int tid = threadIdx.x;
    if (tid < NW) {
        float s, c, s0, c0, s1, c1;
        sincosf(0.5f * rx0[tid], &s,  &c);
        sincosf(0.5f * ry0[tid], &s0, &c0);
        sincosf(0.5f * ry1[tid], &s1, &c1);
        const float ar =  c0 * c;
        const float ai =  s0 * s;
        const float br = -s0 * c;
        const float bi = -c0 * s;
        cl1[tid][0] = pkb(ar);
        cl1[tid][1] = pk(-ai,  ai);
        cl1[tid][2] = pk( ai, -ai);
        cl1[tid][3] = pkb(br);
        cl1[tid][4] = pkb(-br);
        cl1[tid][5] = pk(-bi, bi);
        cry[tid][0] = pkb(c1);
        cry[tid][1] = pkb(s1);
        cry[tid][2] = pkb(-s1);
        if (tid == 0) {
            cw0[0] = pk( ar,  ai);
            cw0[1] = pk( br,  bi);
            cw0[2] = pk(-br,  bi);
            cw0[3] = pk( ar, -ai);
        }
    }
    __syncthreads();

    const int w = tid >> 5;
    const int t = tid & 31;
    const int n = blockIdx.x * WARPS_PER_BLK + w;   // state 0..4095
    u64* sb = buf[w];

    // ---- Load. a[r] = (v, v) packed; sumsq accumulated packed (both lanes equal). ----
    u64 a[32];
    const float* xr = x + (size_t)n * DIM;
    u64 sq = 0ull;
#pragma unroll
    for (int r = 0; r < 32; ++r) {
        a[r] = pkb(xr[(r << 5) + t]);
        sq = f2fma(a[r], a[r], sq);
    }
    float sumsq, dummy;
    upk(sq, sumsq, dummy);
#pragma unroll
    for (int off = 16; off; off >>= 1)
        sumsq += __shfl_xor_sync(0xffffffffu, sumsq, off);
    const float inv = 1.f / fmaxf(sqrtf(sumsq), 1e-12f);

    // ---- Phase A: fused layer-1 on wires 0..4 (wire q -> reg bit K=4-q) ----
    {   // wire 0 (K=4), specialized for purely-real input; normalization folded in.
        const u64 pinv = pkb(inv);
        const u64 pa = f2mul(ldsv(cw0 + 0), pinv), pb = f2mul(ldsv(cw0 + 1), pinv);
        const u64 pc = f2mul(ldsv(cw0 + 2), pinv), pd = f2mul(ldsv(cw0 + 3), pinv);
#pragma unroll
        for (int p = 0; p < 16; ++p) {
            u64 a0 = a[p], a1 = a[p + 16];      // both lanes hold the raw real value
            a[p]      = f2fma(a0, pa, f2mul(a1, pb));
            a[p + 16] = f2fma(a0, pc, f2mul(a1, pd));
        }
    }
    l1c<3>(a, cl1[1]);
    l1c<2>(a, cl1[2]);
    l1c<1>(a, cl1[3]);
    l1c<0>(a, cl1[4]);

    // ---- Remap LA -> LB (transpose) ----
    __syncwarp();
#pragma unroll
    for (int r = 0; r < 32; ++r) sb[swz((r << 5) | t)] = a[r];
    __syncwarp();
#pragma unroll
    for (int r = 0; r < 32; ++r) a[r] = sb[swz((t << 5) | r)];

    // ---- Phase B: fused layer-1 on wires 5..9 (wire q -> reg bit K=9-q) ----
    l1c<4>(a, cl1[5]);
    l1c<3>(a, cl1[6]);
    l1c<2>(a, cl1[7]);
    l1c<1>(a, cl1[8]);
    l1c<0>(a, cl1[9]);

    // ---- Remap LB -> LA with the CNOT-ring gather folded in ----
    __syncwarp();
#pragma unroll
    for (int r = 0; r < 32; ++r) sb[swz((t << 5) | r)] = a[r];
    __syncwarp();
#pragma unroll
    for (int r = 0; r < 32; ++r) a[r] = sb[swz(cnot_gather((r << 5) | t))];

    // ---- Phase C: layer-2 RY on wires 0..4 ----
    ryc<4>(a, cry[0]);
    ryc<3>(a, cry[1]);
    ryc<2>(a, cry[2]);
    ryc<1>(a, cry[3]);
    ryc<0>(a, cry[4]);

    // ---- Remap LA -> LB (transpose) ----
    __syncwarp();
#pragma unroll
    for (int r = 0; r < 32; ++r) sb[swz((r << 5) | t)] = a[r];
    __syncwarp();
#pragma unroll
    for (int r = 0; r < 32; ++r) a[r] = sb[swz((t << 5) | r)];

    // ---- Phase D: layer-2 RY on wires 5..9 ----
    ryc<4>(a, cry[5]);
    ryc<3>(a, cry[6]);
    ryc<2>(a, cry[7]);
    ryc<1>(a, cry[8]);
    ryc<0>(a, cry[9]);

    // ---- Z expectations. Layout LB: i = (t<<5)|r. Packed (re^2, im^2) accum. ----
    u64 tot = 0, S0 = 0, S1 = 0, S2 = 0, S3 = 0, S4 = 0;
    const u64 NEG1 = pkb(-1.0f);
#pragma unroll
    for (int r = 0; r < 32; ++r) {
        u64 p = f2mul(a[r], a[r]);                  // (re^2, im^2)
        tot = f2add(tot, p);
        S0 = (r & 1)  ? f2fma(p, NEG1, S0) : f2add(S0, p);
        S1 = (r & 2)  ? f2fma(p, NEG1, S1) : f2add(S1, p);
        S2 = (r & 4)  ? f2fma(p, NEG1, S2) : f2add(S2, p);
        S3 = (r & 8)  ? f2fma(p, NEG1, S3) : f2add(S3, p);
        S4 = (r & 16) ? f2fma(p, NEG1, S4) : f2add(S4, p);
    }
    // horizontal: prob = re^2 + im^2
    float vals[10];
    {
        float xx, yy;
        upk(tot, xx, yy); float ft = xx + yy;
        vals[0] = (t & 16) ? -ft : ft;   // wire 0: t bit 4
        vals[1] = (t & 8)  ? -ft : ft;
        vals[2] = (t & 4)  ? -ft : ft;
        vals[3] = (t & 2)  ? -ft : ft;
        vals[4] = (t & 1)  ? -ft : ft;
        upk(S4, xx, yy); vals[5] = xx + yy;   // wire 5: r bit 4
        upk(S3, xx, yy); vals[6] = xx + yy;
        upk(S2, xx, yy); vals[7] = xx + yy;
        upk(S1, xx, yy); vals[8] = xx + yy;
        upk(S0, xx, yy); vals[9] = xx + yy;
    }
#pragma unroll
    for (int off = 16; off; off >>= 1) {
#pragma unroll
        for (int j = 0; j < 10; ++j)
            vals[j] += __shfl_xor_sync(0xffffffffu, vals[j], off);
    }
    if (t == 0) {
#pragma unroll
        for (int j = 0; j < 10; ++j) out[(size_t)n * NW + j] = vals[j];
    }
}

extern "C" void kernel_launch(void* const* d_in, const int* in_sizes, int n_in,
                              void* d_out, int out_size) {
    const float* x   = (const float*)d_in[0];
    const float* rx0 = (const float*)d_in[1];
    const float* ry0 = (const float*)d_in[2];
    const float* ry1 = (const float*)d_in[3];
    float* out = (float*)d_out;
    const int n_states = in_sizes[0] / DIM;            // 4096
    qsa5_kernel<<<n_states / WARPS_PER_BLK, 32 * WARPS_PER_BLK>>>(x, rx0, ry0, ry1, out);
}